// round 11
// baseline (speedup 1.0000x reference)
#include <cuda_runtime.h>

// DenseWarpLayer: bilinear warp, N=8, H=512, W=512, C=32 fp32.
// R11 = R10 (persistent single-wave grid, 8 threads/pixel full-128B-line
// warp accesses, 2 sequential pixels/task, 32 regs / 8 blocks / 64 warps,
// 1-ahead L1 flow prefetch) + 3-ahead L2 flow prefetch, so the 1-ahead L1
// prefetch hits L2 instead of DRAM. Zero register cost; all prior levers
// measured: occupancy/95% (R9: flat), L2->L1 gather conversion (R6: flat),
// cp.async in-flight bytes (R8: worse), register ILP (R2/R3/R7: worse),
// flow latency removal (R10: +1%). Kernel is at the mixed-R/W DRAM
// efficiency ceiling (~70% of 8TB/s) with traffic at the compulsory floor.

#define N_ 8
#define H_ 512
#define W_ 512
#define C4_ 8u            // 32 channels = 8 float4
#define ROW4 (W_ * C4_)   // float4 per image row = 4096
#define NBLOCKS 1184u     // 148 SMs * 8 blocks -> exactly one wave
#define NTHREADS (NBLOCKS * 256u)
#define NTASKS 8388608u   // N*H*W*8 / 2 pixel-pair tasks
#define PIX_STRIDE 75776u // pixel offset between successive iterations
#define MAX_PIX 2097151u  // N*H*W - 1

__device__ __forceinline__ unsigned gather_base(unsigned pix, unsigned c4,
                                                const float2 fl,
                                                float& ax, float& ay)
{
    const unsigned w = pix & (W_ - 1);
    const unsigned h = (pix >> 9) & (H_ - 1);
    const unsigned n = pix >> 18;

    const float qy = (float)h - fl.x;
    const float qx = (float)w - fl.y;

    float fyf = floorf(qy);
    float fxf = floorf(qx);
    fyf = fminf(fmaxf(fyf, 0.0f), (float)(H_ - 2));
    fxf = fminf(fmaxf(fxf, 0.0f), (float)(W_ - 2));

    ay = fminf(fmaxf(qy - fyf, 0.0f), 1.0f);
    ax = fminf(fmaxf(qx - fxf, 0.0f), 1.0f);

    return ((n * H_ + (unsigned)(int)fyf) * W_ + (unsigned)(int)fxf) * C4_ + c4;
}

__device__ __forceinline__ float4 bilerp4(const float4 tl, const float4 tr,
                                          const float4 bl, const float4 br,
                                          const float ax, const float ay)
{
    float4 r; float top, bot;
    top = tl.x + ax * (tr.x - tl.x); bot = bl.x + ax * (br.x - bl.x);
    r.x = top + ay * (bot - top);
    top = tl.y + ax * (tr.y - tl.y); bot = bl.y + ax * (br.y - bl.y);
    r.y = top + ay * (bot - top);
    top = tl.z + ax * (tr.z - tl.z); bot = bl.z + ax * (br.z - bl.z);
    r.z = top + ay * (bot - top);
    top = tl.w + ax * (tr.w - tl.w); bot = bl.w + ax * (br.w - bl.w);
    r.w = top + ay * (bot - top);
    return r;
}

__device__ __forceinline__ void do_pixel(const float4* __restrict__ img4,
                                         float4* __restrict__ out4,
                                         unsigned pix, unsigned c4,
                                         const float2 fl)
{
    float ax, ay;
    const unsigned rb = gather_base(pix, c4, fl, ax, ay);

    const float4 tl = __ldg(img4 + rb);
    const float4 tr = __ldg(img4 + rb + C4_);
    const float4 bl = __ldg(img4 + rb + ROW4);
    const float4 br = __ldg(img4 + rb + ROW4 + C4_);

    out4[pix * C4_ + c4] = bilerp4(tl, tr, bl, br, ax, ay);
}

__global__ __launch_bounds__(256, 8)
void dense_warp_kernel(const float* __restrict__ image,
                       const float* __restrict__ flow,
                       float* __restrict__ out)
{
    const float2* fl2  = reinterpret_cast<const float2*>(flow);
    const float4* img4 = reinterpret_cast<const float4*>(image);
    float4*       out4 = reinterpret_cast<float4*>(out);

    const unsigned tid0 = blockIdx.x * 256u + threadIdx.x;

    #pragma unroll 1
    for (unsigned task = tid0; task < NTASKS; task += NTHREADS) {
        const unsigned c4   = task & 7u;
        const unsigned slot = task >> 3;
        const unsigned grp  = slot >> 2;
        const unsigned r    = slot & 3u;
        const unsigned pix0 = grp * 8u + r;
        const unsigned pix1 = pix0 + 4u;

        // two-level flow prefetch pipeline (zero payload registers):
        //  - 3 iterations ahead into L2 (stages the DRAM fetch early)
        //  - 1 iteration ahead into L1 (hits L2 thanks to the stage above)
        {
            const unsigned p1 = min(pix0 + PIX_STRIDE, MAX_PIX);
            const unsigned p3 = min(pix0 + 3u * PIX_STRIDE, MAX_PIX);
            asm volatile("prefetch.global.L2 [%0];" :: "l"(fl2 + p3));
            asm volatile("prefetch.global.L1 [%0];" :: "l"(fl2 + p1));
        }

        // this iteration's flows (L1 hits after warm-up)
        const float2 fl0 = __ldg(fl2 + pix0);
        const float2 fl1 = __ldg(fl2 + pix1);

        do_pixel(img4, out4, pix0, c4, fl0);
        do_pixel(img4, out4, pix1, c4, fl1);
    }
}

extern "C" void kernel_launch(void* const* d_in, const int* in_sizes, int n_in,
                              void* d_out, int out_size)
{
    const float* image = (const float*)d_in[0];
    const float* flow  = (const float*)d_in[1];
    float* out = (float*)d_out;

    dense_warp_kernel<<<NBLOCKS, 256>>>(image, flow, out);
}

// round 12
// speedup vs baseline: 1.3692x; 1.3692x over previous
#include <cuda_runtime.h>

// DenseWarpLayer: bilinear warp, N=8, H=512, W=512, C=32 fp32.
// R12 = exact revert to R10, the best measured configuration (92.2us):
// persistent single-wave grid (1184 blocks = 148 SMs x 8), 8 threads/pixel
// so every warp-level LDG.128/STG.128 covers 4 full 128B lines, 2 sequential
// pixels per task with both flow loads hoisted, 32 regs / 8 blocks / 64
// warps per SM, and a 1-iteration-ahead L1 flow prefetch (dedups in L1,
// zero payload registers).
//
// Optimization ledger (all measured on GB300):
//   register ILP (R2/R3/R7)        -> worse (occupancy cliff at 32 regs)
//   cp.async smem pipeline (R8)    -> worse (regs + double L1 crossing)
//   L2->L1 gather conversion (R6)  -> flat (hit latency not binding)
//   occupancy 83->95% (R9)         -> ~flat (+1%)
//   flow L1 prefetch (R10)         -> +1%  (kept)
//   deeper L2 prefetch (R11)       -> 37% WORSE (redundant LTS traffic)
// Kernel sits at compulsory traffic (~510MB) x mixed-R/W HBM ceiling
// (~69% of 8TB/s); no SM-side unit is saturated.

#define N_ 8
#define H_ 512
#define W_ 512
#define C4_ 8u            // 32 channels = 8 float4
#define ROW4 (W_ * C4_)   // float4 per image row = 4096
#define NBLOCKS 1184u     // 148 SMs * 8 blocks -> exactly one wave
#define NTHREADS (NBLOCKS * 256u)
#define NTASKS 8388608u   // N*H*W*8 / 2 pixel-pair tasks
#define PIX_STRIDE 75776u // pixel offset between successive iterations
#define MAX_PIX 2097151u  // N*H*W - 1

__device__ __forceinline__ unsigned gather_base(unsigned pix, unsigned c4,
                                                const float2 fl,
                                                float& ax, float& ay)
{
    const unsigned w = pix & (W_ - 1);
    const unsigned h = (pix >> 9) & (H_ - 1);
    const unsigned n = pix >> 18;

    const float qy = (float)h - fl.x;
    const float qx = (float)w - fl.y;

    float fyf = floorf(qy);
    float fxf = floorf(qx);
    fyf = fminf(fmaxf(fyf, 0.0f), (float)(H_ - 2));
    fxf = fminf(fmaxf(fxf, 0.0f), (float)(W_ - 2));

    ay = fminf(fmaxf(qy - fyf, 0.0f), 1.0f);
    ax = fminf(fmaxf(qx - fxf, 0.0f), 1.0f);

    return ((n * H_ + (unsigned)(int)fyf) * W_ + (unsigned)(int)fxf) * C4_ + c4;
}

__device__ __forceinline__ float4 bilerp4(const float4 tl, const float4 tr,
                                          const float4 bl, const float4 br,
                                          const float ax, const float ay)
{
    float4 r; float top, bot;
    top = tl.x + ax * (tr.x - tl.x); bot = bl.x + ax * (br.x - bl.x);
    r.x = top + ay * (bot - top);
    top = tl.y + ax * (tr.y - tl.y); bot = bl.y + ax * (br.y - bl.y);
    r.y = top + ay * (bot - top);
    top = tl.z + ax * (tr.z - tl.z); bot = bl.z + ax * (br.z - bl.z);
    r.z = top + ay * (bot - top);
    top = tl.w + ax * (tr.w - tl.w); bot = bl.w + ax * (br.w - bl.w);
    r.w = top + ay * (bot - top);
    return r;
}

__device__ __forceinline__ void do_pixel(const float4* __restrict__ img4,
                                         float4* __restrict__ out4,
                                         unsigned pix, unsigned c4,
                                         const float2 fl)
{
    float ax, ay;
    const unsigned rb = gather_base(pix, c4, fl, ax, ay);

    const float4 tl = __ldg(img4 + rb);
    const float4 tr = __ldg(img4 + rb + C4_);
    const float4 bl = __ldg(img4 + rb + ROW4);
    const float4 br = __ldg(img4 + rb + ROW4 + C4_);

    out4[pix * C4_ + c4] = bilerp4(tl, tr, bl, br, ax, ay);
}

__global__ __launch_bounds__(256, 8)
void dense_warp_kernel(const float* __restrict__ image,
                       const float* __restrict__ flow,
                       float* __restrict__ out)
{
    const float2* fl2  = reinterpret_cast<const float2*>(flow);
    const float4* img4 = reinterpret_cast<const float4*>(image);
    float4*       out4 = reinterpret_cast<float4*>(out);

    const unsigned tid0 = blockIdx.x * 256u + threadIdx.x;

    #pragma unroll 1
    for (unsigned task = tid0; task < NTASKS; task += NTHREADS) {
        const unsigned c4   = task & 7u;
        const unsigned slot = task >> 3;
        const unsigned grp  = slot >> 2;
        const unsigned r    = slot & 3u;
        const unsigned pix0 = grp * 8u + r;
        const unsigned pix1 = pix0 + 4u;

        // prefetch NEXT iteration's flow line (covers both its pixels'
        // float2 values: +32B apart, always same 128B line). Clamped so the
        // final iteration prefetches a valid in-buffer address.
        {
            const unsigned npix = min(pix0 + PIX_STRIDE, MAX_PIX);
            asm volatile("prefetch.global.L1 [%0];" :: "l"(fl2 + npix));
        }

        // this iteration's flows (L1/L2 hits after warm-up)
        const float2 fl0 = __ldg(fl2 + pix0);
        const float2 fl1 = __ldg(fl2 + pix1);

        do_pixel(img4, out4, pix0, c4, fl0);
        do_pixel(img4, out4, pix1, c4, fl1);
    }
}

extern "C" void kernel_launch(void* const* d_in, const int* in_sizes, int n_in,
                              void* d_out, int out_size)
{
    const float* image = (const float*)d_in[0];
    const float* flow  = (const float*)d_in[1];
    float* out = (float*)d_out;

    dense_warp_kernel<<<NBLOCKS, 256>>>(image, flow, out);
}